// round 15
// baseline (speedup 1.0000x reference)
#include <cuda_runtime.h>

// SNN forward: T=1000, B=8192, I=9, H=96, O=3
// 4 batches/warp (2 sets A/B), CTA=128 (4 warps), grid=512 -> single wave.
// v = beta*mem1 + b1 - spk1 fusion; FSET spikes; x pipeline depth 2 (4-buf ring).
// R15: syncwarp every 2 iters (depth-2 ring makes it safe), head shuffles issued
// early (interleaved with x load/stage), packed A/B lo+hi sums (3 fadd2).

#define T_STEPS 1000
#define BATCHN  8192
#define BETA    0.92f

typedef unsigned long long u64;

static __device__ __forceinline__ u64 pk2(float lo, float hi) {
    u64 r; asm("mov.b64 %0,{%1,%2};" : "=l"(r) : "f"(lo), "f"(hi)); return r;
}
static __device__ __forceinline__ void upk2(u64 v, float& a, float& b) {
    asm("mov.b64 {%0,%1},%2;" : "=f"(a), "=f"(b) : "l"(v));
}
static __device__ __forceinline__ u64 ffma2(u64 a, u64 b, u64 c) {
    u64 d; asm("fma.rn.f32x2 %0,%1,%2,%3;" : "=l"(d) : "l"(a), "l"(b), "l"(c)); return d;
}
static __device__ __forceinline__ u64 fadd2(u64 a, u64 b) {
    u64 d; asm("add.rn.f32x2 %0,%1,%2;" : "=l"(d) : "l"(a), "l"(b)); return d;
}
static __device__ __forceinline__ u64 fmul2(u64 a, u64 b) {
    u64 d; asm("mul.rn.f32x2 %0,%1,%2;" : "=l"(d) : "l"(a), "l"(b)); return d;
}
static __device__ __forceinline__ float setgt1(float a) {
    float d; asm("set.gt.f32.f32 %0,%1,%2;" : "=f"(d) : "f"(a), "f"(1.0f)); return d;
}
static __device__ __forceinline__ u64 shflx64(u64 v, int m) {
    unsigned lo = (unsigned)v;
    unsigned hi = (unsigned)(v >> 32);
    lo = __shfl_xor_sync(0xffffffffu, lo, m);
    hi = __shfl_xor_sync(0xffffffffu, hi, m);
    return ((u64)hi << 32) | lo;
}

__global__ void __launch_bounds__(128, 4) snn_kernel(
    const float* __restrict__ x,
    const float* __restrict__ W1,
    const float* __restrict__ b1,
    const float* __restrict__ W2,
    const float* __restrict__ b2,
    float* __restrict__ out)
{
    const int lane = threadIdx.x & 31;
    const int warp = threadIdx.x >> 5;
    const int gw   = blockIdx.x * 4 + warp;
    const int grp  = lane >> 4;
    const int hl   = lane & 15;
    const int hb   = hl * 6;
    const int bA   = gw * 4 + grp;               // set-A batch; set-B = bA + 2

    // x ring: [warp][4 bufs][4 slots x 10 u64]
    __shared__ __align__(16) u64 xs[4][4][40];

    u64 w1p[3][9];
    #pragma unroll
    for (int j = 0; j < 3; j++)
        #pragma unroll
        for (int i = 0; i < 9; i++)
            w1p[j][i] = pk2(W1[(hb + 2*j) * 9 + i], W1[(hb + 2*j + 1) * 9 + i]);

    u64 w2p[3][3];
    #pragma unroll
    for (int o = 0; o < 3; o++)
        #pragma unroll
        for (int j = 0; j < 3; j++)
            w2p[o][j] = pk2(W2[o * 96 + hb + 2*j], W2[o * 96 + hb + 2*j + 1]);

    u64 b1p[3];
    #pragma unroll
    for (int j = 0; j < 3; j++) b1p[j] = pk2(b1[hb + 2*j], b1[hb + 2*j + 1]);

    const u64 BET2 = pk2(BETA, BETA);
    const u64 NEG1 = pk2(-1.0f, -1.0f);

    const int  oc        = (hl >> 2) > 2 ? 2 : (hl >> 2);
    const bool fin_store = ((hl & 3) < 2) && (hl < 12);
    const bool is_spk    = (hl & 3) == 0;
    const u64  BIAS2     = pk2(b2[oc], b2[oc]);

    float* optr = (is_spk ? out : out + (size_t)T_STEPS * BATCHN * 3)
                  + (size_t)bA * 3 + oc;

    u64 vA0 = b1p[0], vA1 = b1p[1], vA2 = b1p[2];
    u64 vB0 = b1p[0], vB1 = b1p[1], vB2 = b1p[2];
    u64 m2 = 0ull, sp2 = 0ull, pp = 0ull;        // packed (A,B) layer-2 state

    // ---- x loaders: 36 contiguous floats per warp-step ----
    const int  idx0 = lane;
    const int  off0 = (idx0 / 9) * 10 + idx0 % 9;
    const bool l2   = lane < 4;
    const int  idx1 = 32 + lane;
    const int  off1 = (idx1 / 9) * 10 + idx1 % 9;
    const float* p0 = x + (size_t)gw * 36 + idx0;
    const float* p1 = x + (size_t)gw * 36 + idx1;
    const size_t xstr = (size_t)BATCHN * 9;

    // prologue: buffers 0,1 filled; x(2),x(3) in flight in registers
    {
        float v0l = p0[0];
        xs[warp][0][off0] = pk2(v0l, v0l);
        float v1l = p0[xstr];
        xs[warp][1][off0] = pk2(v1l, v1l);
        if (l2) {
            float w0l = p1[0];
            xs[warp][0][off1] = pk2(w0l, w0l);
            float w1l = p1[xstr];
            xs[warp][1][off1] = pk2(w1l, w1l);
        }
    }
    float rEa = p0[2 * xstr];
    float rEb = l2 ? p1[2 * xstr] : 0.f;
    float rOa = p0[3 * xstr];
    float rOb = l2 ? p1[3 * xstr] : 0.f;
    __syncwarp();

    // ===================== shared body pieces as macros =====================
#define LOAD_XP(xp, slot, buf)                                                  \
    {                                                                           \
        const ulonglong2* q = reinterpret_cast<const ulonglong2*>((buf) + (slot) * 10); \
        ulonglong2 q0 = q[0], q1 = q[1], q2 = q[2], q3 = q[3];                  \
        xp[0] = q0.x; xp[1] = q0.y; xp[2] = q1.x; xp[3] = q1.y;                 \
        xp[4] = q2.x; xp[5] = q2.y; xp[6] = q3.x; xp[7] = q3.y;                 \
        xp[8] = (buf)[(slot) * 10 + 8];                                         \
    }

#define SET_COMPUTE(xp, v0, v1, v2, c_0, c_1, c_2)                              \
    {                                                                           \
        u64 a0 = v0, a1 = v1, a2 = v2;                                          \
        _Pragma("unroll")                                                       \
        for (int i = 0; i < 9; i++) {                                           \
            a0 = ffma2(w1p[0][i], xp[i], a0);                                   \
            a1 = ffma2(w1p[1][i], xp[i], a1);                                   \
            a2 = ffma2(w1p[2][i], xp[i], a2);                                   \
        }                                                                       \
        float f0, f1;                                                           \
        upk2(a0, f0, f1);                                                       \
        u64 s0 = pk2(setgt1(f0), setgt1(f1));                                   \
        upk2(a1, f0, f1);                                                       \
        u64 s1 = pk2(setgt1(f0), setgt1(f1));                                   \
        upk2(a2, f0, f1);                                                       \
        u64 s2 = pk2(setgt1(f0), setgt1(f1));                                   \
        v0 = ffma2(BET2, a0, ffma2(s0, NEG1, b1p[0]));                          \
        v1 = ffma2(BET2, a1, ffma2(s1, NEG1, b1p[1]));                          \
        v2 = ffma2(BET2, a2, ffma2(s2, NEG1, b1p[2]));                          \
        c_0 = fmul2(s0, w2p[0][0]); c_0 = ffma2(s1, w2p[0][1], c_0); c_0 = ffma2(s2, w2p[0][2], c_0); \
        c_1 = fmul2(s0, w2p[1][0]); c_1 = ffma2(s1, w2p[1][1], c_1); c_1 = ffma2(s2, w2p[1][2], c_1); \
        c_2 = fmul2(s0, w2p[2][0]); c_2 = ffma2(s1, w2p[2][1], c_2); c_2 = ffma2(s2, w2p[2][2], c_2); \
    }

#define STAGE_PREFETCH(t)                                                       \
    {                                                                           \
        float ra = ((t) & 1) ? rOa : rEa;                                       \
        float rb = ((t) & 1) ? rOb : rEb;                                       \
        u64* stg = xs[warp][((t) + 2) & 3];                                     \
        stg[off0] = pk2(ra, ra);                                                \
        if (l2) stg[off1] = pk2(rb, rb);                                        \
        int tn = ((t) + 4 < T_STEPS) ? ((t) + 4) : (T_STEPS - 1);               \
        float na = p0[(size_t)tn * xstr];                                       \
        float nb = l2 ? p1[(size_t)tn * xstr] : 0.f;                            \
        if ((t) & 1) { rOa = na; rOb = nb; } else { rEa = na; rEb = nb; }       \
    }

    // pack (A,B) sums: P_o = (loA+hiA, loB+hiB) via fadd2 on repacked halves
#define TAIL_REDUCE()                                                           \
    {                                                                           \
        float alo, ahi, blo, bhi;                                               \
        upk2(cA0, alo, ahi); upk2(cB0, blo, bhi);                               \
        u64 P0 = fadd2(pk2(alo, blo), pk2(ahi, bhi));                           \
        upk2(cA1, alo, ahi); upk2(cB1, blo, bhi);                               \
        u64 P1 = fadd2(pk2(alo, blo), pk2(ahi, bhi));                           \
        upk2(cA2, alo, ahi); upk2(cB2, blo, bhi);                               \
        u64 P2 = fadd2(pk2(alo, blo), pk2(ahi, bhi));                           \
        P0 = fadd2(P0, shflx64(P0, 8));                                         \
        P1 = fadd2(P1, shflx64(P1, 8));                                         \
        P2 = fadd2(P2, shflx64(P2, 8));                                         \
        P0 = fadd2(P0, shflx64(P0, 4));                                         \
        P1 = fadd2(P1, shflx64(P1, 4));                                         \
        P2 = fadd2(P2, shflx64(P2, 4));                                         \
        pp = (oc == 0) ? P0 : ((oc == 1) ? P1 : P2);                            \
    }

    // ---- peeled body t = 0 (no head, no trailing sync: t=0 is even) ----
    {
        u64 xpA[9];
        LOAD_XP(xpA, grp, xs[warp][0]);
        STAGE_PREFETCH(0);
        u64 cA0, cA1, cA2, cB0, cB1, cB2;
        SET_COMPUTE(xpA, vA0, vA1, vA2, cA0, cA1, cA2);
        {
            u64 xpB[9];
            LOAD_XP(xpB, grp + 2, xs[warp][0]);
            SET_COMPUTE(xpB, vB0, vB1, vB2, cB0, cB1, cB2);
        }
        TAIL_REDUCE();
    }

    #pragma unroll 4
    for (int t = 1; t < T_STEPS; t++) {
        u64* base = xs[warp][t & 3];

        // head shuffle level 1 issued first; x loads/stage fill its latency
        u64 h1 = shflx64(pp, 2);

        u64 xpA[9];
        LOAD_XP(xpA, grp, base);

        u64 sv = fadd2(pp, h1);
        u64 h2 = shflx64(sv, 1);

        STAGE_PREFETCH(t);

        // ---- finalize step t-1 (packed over A,B) ----
        {
            sv = fadd2(sv, h2);
            u64 mm = ffma2(sp2, NEG1, ffma2(BET2, m2, fadd2(BIAS2, sv)));
            m2 = mm;
            float mmA, mmB;
            upk2(mm, mmA, mmB);
            float sa = setgt1(mmA), sb = setgt1(mmB);
            sp2 = pk2(sa, sb);
            if (fin_store) {
                __stcs(optr,     is_spk ? sa : mmA);
                __stcs(optr + 6, is_spk ? sb : mmB);
            }
            optr += 3 * BATCHN;
        }

        if (t & 1) __syncwarp();   // sync every 2 iters: depth-2 ring makes this safe

        u64 cA0, cA1, cA2, cB0, cB1, cB2;
        SET_COMPUTE(xpA, vA0, vA1, vA2, cA0, cA1, cA2);
        {
            u64 xpB[9];
            LOAD_XP(xpB, grp + 2, base);
            SET_COMPUTE(xpB, vB0, vB1, vB2, cB0, cB1, cB2);
        }
        TAIL_REDUCE();
    }

    // ---- epilogue: finalize timestep T-1 ----
    {
        u64 sv = fadd2(pp, shflx64(pp, 2));
        sv = fadd2(sv, shflx64(sv, 1));
        u64 mm = ffma2(sp2, NEG1, ffma2(BET2, m2, fadd2(BIAS2, sv)));
        float mmA, mmB;
        upk2(mm, mmA, mmB);
        if (fin_store) {
            __stcs(optr,     is_spk ? setgt1(mmA) : mmA);
            __stcs(optr + 6, is_spk ? setgt1(mmB) : mmB);
        }
    }

#undef LOAD_XP
#undef SET_COMPUTE
#undef STAGE_PREFETCH
#undef TAIL_REDUCE
}

extern "C" void kernel_launch(void* const* d_in, const int* in_sizes, int n_in,
                              void* d_out, int out_size) {
    const float* x  = (const float*)d_in[0];
    const float* W1 = (const float*)d_in[1];
    const float* b1 = (const float*)d_in[2];
    const float* W2 = (const float*)d_in[3];
    const float* b2 = (const float*)d_in[4];
    float* out = (float*)d_out;

    // 8192 batches / (4 per warp * 4 warps) = 512 CTAs of 128 threads -> 1 wave
    snn_kernel<<<512, 128>>>(x, W1, b1, W2, b2, out);
}